// round 6
// baseline (speedup 1.0000x reference)
#include <cuda_runtime.h>
#include <cuda_bf16.h>
#include <cstdint>

using bf16 = __nv_bfloat16;

static constexpr int B_=4, T_=1024, C_=768, H_=12;
static constexpr long BT=4096, YN=BT*C_, AN=48L*1024*1024;
static constexpr float SHIFT = 20.0f;

__device__ __align__(1024) bf16 g_xh[YN], g_xl[YN];
__device__ __align__(1024) bf16 g_wqh[2304L*768], g_wql[2304L*768];
__device__ __align__(1024) bf16 g_wph[768L*768],  g_wpl[768L*768];
__device__ __align__(1024) bf16 g_qh[YN], g_ql[YN], g_kh[YN], g_kl[YN];
__device__ __align__(1024) bf16 g_vh[YN], g_vl[YN], g_vth[YN], g_vtl[YN];
__device__ __align__(1024) float g_attn_fb[AN];          // fallback attn target
__device__ __align__(1024) bf16 g_ah[AN], g_al[AN];      // unnormalized exp hi/lo
__device__ __align__(1024) bf16 g_yh[YN], g_yl[YN];
__device__ __align__(1024) float g_rowsum[48*1024];

// ---------------- helpers ----------------
__device__ __forceinline__ uint32_t smem_u32(const void* p){
    uint32_t a; asm("{ .reg .u64 t; cvta.to.shared.u64 t, %1; cvt.u32.u64 %0, t; }":"=r"(a):"l"(p)); return a;
}
__device__ __forceinline__ void mma16816(float* c, const uint32_t* a, const uint32_t* b){
    asm volatile("mma.sync.aligned.m16n8k16.row.col.f32.bf16.bf16.f32 "
        "{%0,%1,%2,%3}, {%4,%5,%6,%7}, {%8,%9}, {%0,%1,%2,%3};"
        : "+f"(c[0]),"+f"(c[1]),"+f"(c[2]),"+f"(c[3])
        : "r"(a[0]),"r"(a[1]),"r"(a[2]),"r"(a[3]),"r"(b[0]),"r"(b[1]));
}
__device__ __forceinline__ void ldsm4(uint32_t* r, uint32_t addr){
    asm volatile("ldmatrix.sync.aligned.m8n8.x4.shared.b16 {%0,%1,%2,%3}, [%4];"
        : "=r"(r[0]),"=r"(r[1]),"=r"(r[2]),"=r"(r[3]) : "r"(addr));
}
__device__ __forceinline__ void ldsm2(uint32_t* r, uint32_t addr){
    asm volatile("ldmatrix.sync.aligned.m8n8.x2.shared.b16 {%0,%1}, [%2];"
        : "=r"(r[0]),"=r"(r[1]) : "r"(addr));
}
__device__ __forceinline__ void cpasync16(uint32_t dst, const void* src){
    asm volatile("cp.async.cg.shared.global [%0], [%1], 16;" :: "r"(dst), "l"(src));
}
__device__ __forceinline__ void cpcommit(){ asm volatile("cp.async.commit_group;" ::: "memory"); }
template<int N> __device__ __forceinline__ void cpwait(){ asm volatile("cp.async.wait_group %0;" :: "n"(N) : "memory"); }
__device__ __forceinline__ uint32_t pack_bf(float a, float b){
    __nv_bfloat162 t = __floats2bfloat162_rn(a,b);
    return *reinterpret_cast<uint32_t*>(&t);
}
__device__ __forceinline__ float2 unpack_bf(uint32_t u){
    __nv_bfloat162 t = *reinterpret_cast<__nv_bfloat162*>(&u);
    return make_float2(__bfloat162float(t.x), __bfloat162float(t.y));
}
__device__ __forceinline__ void split2(float v, float& h, float& l){
    bf16 hb = __float2bfloat16(v); h = __bfloat162float(hb); l = v - h;
}

// ---------------------------------------------------------------------------
// TN-form bf16 tensor-core GEMM, 3-product hi/lo split, fused tile loads,
// cp.async double-buffered, smem-staged coalesced epilogue.
// MODE 0:qkv  1:logits->exp  2:proj  3:AV(/rowsum)
// ---------------------------------------------------------------------------
template<int MODE>
__global__ __launch_bounds__(256)
void gemm_tc(const bf16* __restrict__ Ah, const bf16* __restrict__ Al,
             const bf16* __restrict__ Bh, const bf16* __restrict__ Bl,
             const float* __restrict__ bias1, const float* __restrict__ biasM,
             const float* __restrict__ maskM, float* __restrict__ outF,
             float* __restrict__ rowsum,
             bf16* __restrict__ o1h, bf16* __restrict__ o1l,
             bf16* __restrict__ o2h, bf16* __restrict__ o2l,
             bf16* __restrict__ o3h, bf16* __restrict__ o3l)
{
    constexpr int TN  = (MODE==3)?64:128;
    constexpr int NF  = TN/32;
    constexpr int KT  = (MODE==1)?64:((MODE==3)?1024:768);
    constexpr long LDA = (MODE==3)?1024:768;
    constexpr long LDB = (MODE==3)?1024:768;
    constexpr int NKT = KT/32;
    constexpr uint32_t TSA  = 10240u;
    constexpr uint32_t TSB  = TN*80u;
    constexpr uint32_t BUFB = 2u*TSA + 2u*TSB;
    constexpr int P = TN + 4;                  // staging pitch (floats)

    extern __shared__ bf16 smem[];
    const uint32_t sb0 = smem_u32(smem);

    const int tid = threadIdx.x, wid = tid>>5, lane = tid&31;
    const int wr = wid>>2, wc = wid&3;
    const int m_w = wr*64, n_w = wc*(TN/4);
    const int m0 = blockIdx.y*128, n0 = blockIdx.x*TN;
    const int bz = blockIdx.z, bb = bz/H_, hh = bz - bb*H_;

    long aOff, bOff;
    if (MODE==1){ aOff = ((long)bb*1024 + m0)*768 + hh*64; bOff = ((long)bb*1024 + n0)*768 + hh*64; }
    else if (MODE==3){ aOff = (long)bz*1048576 + (long)m0*1024; bOff = (long)bz*65536; }
    else { aOff = (long)m0*LDA; bOff = (long)n0*LDB; }
    const bf16 *pAh=Ah+aOff, *pAl=Al+aOff, *pBh=Bh+bOff, *pBl=Bl+bOff;

    float acc[4][NF][4];
    #pragma unroll
    for(int i=0;i<4;i++)
        #pragma unroll
        for(int j=0;j<NF;j++)
            #pragma unroll
            for(int k=0;k<4;k++) acc[i][j][k]=0.f;

    const uint32_t aAddrB = sb0 + (uint32_t)(m_w + (lane&15))*80u + (uint32_t)(lane>>4)*16u;
    const uint32_t bAddrB = sb0 + (uint32_t)(n_w + (lane&7))*80u + (uint32_t)((lane>>3)&1)*16u;

    auto issue = [&](int kt, int buf){
        const long k0 = (long)kt*32;
        const uint32_t base = sb0 + (uint32_t)buf*BUFB;
        #pragma unroll
        for(int it=0; it<4; ++it){
            const int i = tid + it*256;
            const int t = i>>9, j = i&511, r = j>>2, c = j&3;
            const bf16* src = (t? pAl : pAh) + (long)r*LDA + k0 + c*8;
            cpasync16(base + (uint32_t)t*TSA + (uint32_t)(r*80 + c*16), src);
        }
        #pragma unroll
        for(int it=0; it<TN/32; ++it){
            const int i = tid + it*256;
            const int t = (i >= TN*4);
            const int j = t ? i - TN*4 : i;
            const int r = j>>2, c = j&3;
            const bf16* src = (t? pBl : pBh) + (long)r*LDB + k0 + c*8;
            cpasync16(base + 2u*TSA + (uint32_t)t*TSB + (uint32_t)(r*80 + c*16), src);
        }
        cpcommit();
    };

    issue(0, 0);
    for(int kt=0; kt<NKT; ++kt){
        const int cb = kt&1;
        if (kt+1 < NKT){ issue(kt+1, cb^1); cpwait<1>(); }
        else           { cpwait<0>(); }
        __syncthreads();

        const uint32_t aH = aAddrB + (uint32_t)cb*BUFB;
        const uint32_t aL = aH + TSA;
        const uint32_t bH = bAddrB + (uint32_t)cb*BUFB + 2u*TSA;
        const uint32_t bL = bH + TSB;
        #pragma unroll
        for(int kf=0; kf<2; ++kf){
            uint32_t a4[4][4], b2h[NF][2], b2l[NF][2];
            #pragma unroll
            for(int mf=0; mf<4; ++mf) ldsm4(a4[mf], aH + (uint32_t)mf*1280u + (uint32_t)kf*32u);
            #pragma unroll
            for(int nf=0; nf<NF; ++nf){
                ldsm2(b2h[nf], bH + (uint32_t)nf*640u + (uint32_t)kf*32u);
                ldsm2(b2l[nf], bL + (uint32_t)nf*640u + (uint32_t)kf*32u);
            }
            #pragma unroll
            for(int mf=0; mf<4; ++mf)
                #pragma unroll
                for(int nf=0; nf<NF; ++nf) mma16816(acc[mf][nf], a4[mf], b2h[nf]);
            #pragma unroll
            for(int mf=0; mf<4; ++mf)
                #pragma unroll
                for(int nf=0; nf<NF; ++nf) mma16816(acc[mf][nf], a4[mf], b2l[nf]);
            #pragma unroll
            for(int mf=0; mf<4; ++mf) ldsm4(a4[mf], aL + (uint32_t)mf*1280u + (uint32_t)kf*32u);
            #pragma unroll
            for(int mf=0; mf<4; ++mf)
                #pragma unroll
                for(int nf=0; nf<NF; ++nf) mma16816(acc[mf][nf], a4[mf], b2h[nf]);
        }
        __syncthreads();
    }

    // -------- stage accumulators into smem (fp32) --------
    float* st = reinterpret_cast<float*>(smem);
    const int qd = lane>>2, rr = lane&3;
    #pragma unroll
    for(int mf=0;mf<4;++mf)
        #pragma unroll
        for(int nf=0;nf<NF;++nf)
            #pragma unroll
            for(int h2=0;h2<2;++h2){
                const int mloc = m_w + mf*16 + qd + h2*8;
                const int nc   = n_w + nf*8 + rr*2;
                st[mloc*P + nc]     = acc[mf][nf][h2*2+0];
                st[mloc*P + nc + 1] = acc[mf][nf][h2*2+1];
            }
    __syncthreads();

    // -------- coalesced transform + store pass --------
    constexpr int NIT = 128*TN/1024;
    #pragma unroll
    for(int it2=0; it2<NIT; ++it2){
        const int idx = (it2*256 + tid)*4;
        const int row = idx / TN, col = idx % TN;
        float4 v = *reinterpret_cast<const float4*>(&st[row*P + col]);

        if (MODE==1){
            const long gb = (long)(m0+row)*1024 + n0 + col;
            float4 bm = *reinterpret_cast<const float4*>(biasM + (long)bz*1048576 + gb);
            float4 mk = *reinterpret_cast<const float4*>(maskM + (long)bb*1048576 + gb);
            float e0 = __expf(v.x + bm.x + mk.x - SHIFT);
            float e1 = __expf(v.y + bm.y + mk.y - SHIFT);
            float e2 = __expf(v.z + bm.z + mk.z - SHIFT);
            float e3 = __expf(v.w + bm.w + mk.w - SHIFT);
            float h0,l0,h1,l1,h2,l2,h3,l3;
            split2(e0,h0,l0); split2(e1,h1,l1); split2(e2,h2,l2); split2(e3,h3,l3);
            const long ob = (long)bz*1048576 + gb;
            *reinterpret_cast<uint2*>(o1h + ob) = make_uint2(pack_bf(h0,h1), pack_bf(h2,h3));
            *reinterpret_cast<uint2*>(o1l + ob) = make_uint2(pack_bf(l0,l1), pack_bf(l2,l3));
            float s = e0+e1+e2+e3;
            #pragma unroll
            for(int o=16;o;o>>=1) s += __shfl_xor_sync(0xffffffffu, s, o);
            if (lane==0) atomicAdd(&rowsum[(long)bz*1024 + m0 + row], s);
        } else if (MODE==2){
            const int ng = n0 + col;
            float4 bv = *reinterpret_cast<const float4*>(bias1 + ng);
            v.x += bv.x; v.y += bv.y; v.z += bv.z; v.w += bv.w;
            *reinterpret_cast<float4*>(outF + (long)(m0+row)*768 + ng) = v;
        } else if (MODE==0){
            const int ng = n0 + col;
            float4 bv = *reinterpret_cast<const float4*>(bias1 + ng);
            v.x += bv.x; v.y += bv.y; v.z += bv.z; v.w += bv.w;
            bf16 *dh, *dl; int colb; float scl = 1.f;
            if (n0 < 768)      { dh=o1h; dl=o1l; colb = ng;        scl = 0.125f; }
            else if (n0<1536)  { dh=o2h; dl=o2l; colb = ng-768;  }
            else               { dh=o3h; dl=o3l; colb = ng-1536; }
            v.x*=scl; v.y*=scl; v.z*=scl; v.w*=scl;
            float h0,l0,h1,l1,h2,l2,h3,l3;
            split2(v.x,h0,l0); split2(v.y,h1,l1); split2(v.z,h2,l2); split2(v.w,h3,l3);
            const long ob = (long)(m0+row)*768 + colb;
            *reinterpret_cast<uint2*>(dh + ob) = make_uint2(pack_bf(h0,h1), pack_bf(h2,h3));
            *reinterpret_cast<uint2*>(dl + ob) = make_uint2(pack_bf(l0,l1), pack_bf(l2,l3));
        } else { // MODE 3
            const float inv = 1.0f / rowsum[(long)bz*1024 + m0 + row];
            v.x*=inv; v.y*=inv; v.z*=inv; v.w*=inv;
            float h0,l0,h1,l1,h2,l2,h3,l3;
            split2(v.x,h0,l0); split2(v.y,h1,l1); split2(v.z,h2,l2); split2(v.w,h3,l3);
            const long ob = ((long)bb*1024 + m0 + row)*768 + hh*64 + col;
            *reinterpret_cast<uint2*>(o1h + ob) = make_uint2(pack_bf(h0,h1), pack_bf(h2,h3));
            *reinterpret_cast<uint2*>(o1l + ob) = make_uint2(pack_bf(l0,l1), pack_bf(l2,l3));
        }
    }
}

// attn fp32 output: attn = (eh+el) / rowsum
__global__ __launch_bounds__(256) void attn_write(const bf16* __restrict__ ah, const bf16* __restrict__ al,
                                                  const float* __restrict__ rs, float* __restrict__ attn){
    const long row = blockIdx.x;
    const int tid = threadIdx.x;
    const float inv = 1.0f / rs[row];
    const long o = row*1024 + tid*4;
    uint2 eh = *reinterpret_cast<const uint2*>(ah + o);
    uint2 el = *reinterpret_cast<const uint2*>(al + o);
    float2 h01 = unpack_bf(eh.x), h23 = unpack_bf(eh.y);
    float2 l01 = unpack_bf(el.x), l23 = unpack_bf(el.y);
    float4 v;
    v.x = (h01.x + l01.x)*inv; v.y = (h01.y + l01.y)*inv;
    v.z = (h23.x + l23.x)*inv; v.w = (h23.y + l23.y)*inv;
    *reinterpret_cast<float4*>(attn + o) = v;
}

__global__ __launch_bounds__(256) void zerok(float* __restrict__ p, int n){
    int i = blockIdx.x*256 + threadIdx.x;
    if (i < n) p[i] = 0.f;
}

// fp32 -> bf16 hi/lo elementwise split
__global__ __launch_bounds__(256) void splitk(const float4* __restrict__ in,
                                              bf16* __restrict__ oh, bf16* __restrict__ ol, long n4){
    long i = (long)blockIdx.x*256 + threadIdx.x;
    if (i >= n4) return;
    float4 v = in[i];
    float h0,l0,h1,l1,h2,l2,h3,l3;
    split2(v.x,h0,l0); split2(v.y,h1,l1); split2(v.z,h2,l2); split2(v.w,h3,l3);
    *reinterpret_cast<uint2*>(oh + i*4) = make_uint2(pack_bf(h0,h1), pack_bf(h2,h3));
    *reinterpret_cast<uint2*>(ol + i*4) = make_uint2(pack_bf(l0,l1), pack_bf(l2,l3));
}

// W [K,N] fp32 -> Wt [N,K] bf16 hi/lo
__global__ __launch_bounds__(256) void wtsplit(const float* __restrict__ W,
                                               bf16* __restrict__ oh, bf16* __restrict__ ol, int K, int N){
    __shared__ float tf[32][33];
    const int n0 = blockIdx.x*32, k0 = blockIdx.y*32;
    const int tx = threadIdx.x&31, ty = threadIdx.x>>5;
    #pragma unroll
    for(int i=0;i<4;i++) tf[ty+8*i][tx] = W[(long)(k0+ty+8*i)*N + n0+tx];
    __syncthreads();
    #pragma unroll
    for(int i=0;i<4;i++){
        float v = tf[tx][ty+8*i], h,l; split2(v,h,l);
        long o = (long)(n0+ty+8*i)*K + k0+tx;
        oh[o] = __float2bfloat16(h); ol[o] = __float2bfloat16(l);
    }
}

// v [B,T,H*64] -> vt [B*H, 64, 1024]
__global__ __launch_bounds__(256) void vtrans(const bf16* __restrict__ ih, const bf16* __restrict__ il,
                                              bf16* __restrict__ oh, bf16* __restrict__ ol){
    __shared__ bf16 th[32][34], tl[32][34];
    const int t0 = blockIdx.x*32, d0 = blockIdx.y*32, bz = blockIdx.z;
    const int bb = bz/H_, hh = bz - bb*H_;
    const int tx = threadIdx.x&31, ty = threadIdx.x>>5;
    const long ib = ((long)bb*1024 + t0)*768 + hh*64 + d0;
    #pragma unroll
    for(int i=0;i<4;i++){
        th[ty+8*i][tx] = ih[ib + (long)(ty+8*i)*768 + tx];
        tl[ty+8*i][tx] = il[ib + (long)(ty+8*i)*768 + tx];
    }
    __syncthreads();
    const long ob = ((long)bz*64 + d0)*1024 + t0;
    #pragma unroll
    for(int i=0;i<4;i++){
        oh[ob + (long)(ty+8*i)*1024 + tx] = th[tx][ty+8*i];
        ol[ob + (long)(ty+8*i)*1024 + tx] = tl[tx][ty+8*i];
    }
}

extern "C" void kernel_launch(void* const* d_in, const int* in_sizes, int n_in,
                              void* d_out, int out_size)
{
    const float* x     = (const float*)d_in[0];
    const float* mask  = (const float*)d_in[1];
    const float* bias  = (const float*)d_in[2];
    const float* Wqkv  = (const float*)d_in[3];
    const float* bqkv  = (const float*)d_in[4];
    const float* Wproj = (const float*)d_in[5];
    const float* bproj = (const float*)d_in[6];
    float* out = (float*)d_out;

    bf16 *xh,*xl,*wqh,*wql,*wph,*wpl,*qh,*ql,*kh,*kl,*vh,*vl,*vth,*vtl,*ah,*al,*yh,*yl;
    float *attn_fb, *rowsum;
    cudaGetSymbolAddress((void**)&xh,g_xh);   cudaGetSymbolAddress((void**)&xl,g_xl);
    cudaGetSymbolAddress((void**)&wqh,g_wqh); cudaGetSymbolAddress((void**)&wql,g_wql);
    cudaGetSymbolAddress((void**)&wph,g_wph); cudaGetSymbolAddress((void**)&wpl,g_wpl);
    cudaGetSymbolAddress((void**)&qh,g_qh);   cudaGetSymbolAddress((void**)&ql,g_ql);
    cudaGetSymbolAddress((void**)&kh,g_kh);   cudaGetSymbolAddress((void**)&kl,g_kl);
    cudaGetSymbolAddress((void**)&vh,g_vh);   cudaGetSymbolAddress((void**)&vl,g_vl);
    cudaGetSymbolAddress((void**)&vth,g_vth); cudaGetSymbolAddress((void**)&vtl,g_vtl);
    cudaGetSymbolAddress((void**)&ah,g_ah);   cudaGetSymbolAddress((void**)&al,g_al);
    cudaGetSymbolAddress((void**)&yh,g_yh);   cudaGetSymbolAddress((void**)&yl,g_yl);
    cudaGetSymbolAddress((void**)&attn_fb,g_attn_fb);
    cudaGetSymbolAddress((void**)&rowsum,g_rowsum);

    float* attn = ((long)out_size >= YN + AN) ? (out + YN) : attn_fb;

    const int smemBig = 81920;
    const int smemAV  = 61440;
    cudaFuncSetAttribute(gemm_tc<0>, cudaFuncAttributeMaxDynamicSharedMemorySize, smemBig);
    cudaFuncSetAttribute(gemm_tc<1>, cudaFuncAttributeMaxDynamicSharedMemorySize, smemBig);
    cudaFuncSetAttribute(gemm_tc<2>, cudaFuncAttributeMaxDynamicSharedMemorySize, smemBig);
    cudaFuncSetAttribute(gemm_tc<3>, cudaFuncAttributeMaxDynamicSharedMemorySize, smemAV);

    // 1) split x into bf16 hi/lo; zero rowsum
    splitk<<<(YN/4+255)/256, 256>>>((const float4*)x, xh, xl, YN/4);
    zerok<<<192, 256>>>(rowsum, 48*1024);
    // 2) transpose-split weights to [N,K] hi/lo
    wtsplit<<<dim3(2304/32, 768/32), 256>>>(Wqkv, wqh, wql, 768, 2304);
    wtsplit<<<dim3(768/32, 768/32),  256>>>(Wproj, wph, wpl, 768, 768);
    // 3) qkv GEMM -> q(scaled)/k/v hi+lo
    gemm_tc<0><<<dim3(18,32,1), 256, smemBig>>>(xh, xl, wqh, wql, bqkv, nullptr, nullptr, nullptr,
                                                nullptr, qh, ql, kh, kl, vh, vl);
    // 4) transpose v -> [B*H,64,1024]
    vtrans<<<dim3(32,2,48), 256>>>(vh, vl, vth, vtl);
    // 5) e = exp(q k^T + bias + mask - SHIFT) hi/lo + rowsum
    gemm_tc<1><<<dim3(8,8,48), 256, smemBig>>>(qh, ql, kh, kl, nullptr, bias, mask, nullptr,
                                               rowsum, ah, al, nullptr,nullptr,nullptr,nullptr);
    // 6) attn fp32 = e / rowsum
    attn_write<<<48*1024, 256>>>(ah, al, rowsum, attn);
    // 7) y = (e @ v^T) / rowsum
    gemm_tc<3><<<dim3(1,8,48), 256, smemAV>>>(ah, al, vth, vtl, nullptr, nullptr, nullptr, nullptr,
                                              rowsum, yh, yl, nullptr,nullptr,nullptr,nullptr);
    // 8) out = y @ Wproj + bproj
    gemm_tc<2><<<dim3(6,32,1), 256, smemBig>>>(yh, yl, wph, wpl, bproj, nullptr, nullptr, out,
                                               nullptr, nullptr,nullptr,nullptr,nullptr,nullptr,nullptr);
}